// round 3
// baseline (speedup 1.0000x reference)
#include <cuda_runtime.h>
#include <math.h>

#define N_NODES 100000
#define N_EDGES 1200000
#define KP1 4096
#define KP2 256
#define NEG 0.01f

// ---------------- device scratch (static; no runtime allocation) ----------------
__device__ int   g_src[N_EDGES], g_dst[N_EDGES];
__device__ float g_deg[N_NODES], g_dinv[N_NODES];
__device__ float g_agg3[N_NODES * 3];
__device__ float g_score1[N_NODES];
__device__ int   g_map[N_NODES];
__device__ unsigned g_hist[256];
__device__ unsigned g_prefix;
__device__ int   g_krem;
__device__ int   g_ccount;
__device__ int   g_cand[N_NODES];
__device__ int   g_perm1[KP1];
__device__ float g_psc1[KP1];
__device__ float g_x1p[KP1 * 64];
__device__ int   g_e2s[N_EDGES], g_e2d[N_EDGES];
__device__ int   g_e2cnt;
__device__ float g_deg2[KP1], g_dinv2[KP1];
__device__ float g_agg64[KP1 * 64];
__device__ float g_x2[KP1 * 128];
__device__ float g_agg128[KP1 * 128];
__device__ float g_x3[KP1 * 256];
__device__ float g_score2[KP1];
__device__ int   g_perm2[KP2];
__device__ float g_sc2[KP2];
__device__ float g_v[KP2 * 256];
__device__ float g_invn1, g_invn2;

__device__ __forceinline__ unsigned f2u(float f) {
    unsigned u = __float_as_uint(f);
    return (u & 0x80000000u) ? ~u : (u | 0x80000000u);
}
__device__ __forceinline__ float lrelu(float h) { return (h < 0.f) ? NEG * h : h; }

// ---------------- kernels ----------------

__global__ void k_init(const float* __restrict__ p1, const float* __restrict__ p2) {
    int i = blockIdx.x * blockDim.x + threadIdx.x;
    int stride = gridDim.x * blockDim.x;
    for (int t = i; t < N_NODES; t += stride) { g_deg[t] = 0.f; g_map[t] = -1; }
    for (int t = i; t < N_NODES * 3; t += stride) g_agg3[t] = 0.f;
    for (int t = i; t < KP1; t += stride) g_deg2[t] = 1.0f;
    if (i < 256) g_hist[i] = 0u;
    if (i == 0) {
        g_prefix = 0u; g_krem = KP1; g_ccount = 0; g_e2cnt = 0;
        float s = 0.f;
        for (int j = 0; j < 64; j++) s += p1[j] * p1[j];
        g_invn1 = 1.0f / sqrtf(s);
        s = 0.f;
        for (int j = 0; j < 256; j++) s += p2[j] * p2[j];
        g_invn2 = 1.0f / sqrtf(s);
    }
}

// pass 1 over edges: copy int32 indices + degree
// NOTE: edge_index is int32 (JAX demotes int64 without x64 mode).
__global__ void k_edge_deg(const int* __restrict__ ei) {
    int e = blockIdx.x * blockDim.x + threadIdx.x;
    if (e < N_EDGES) {
        int s = ei[e];
        int d = ei[N_EDGES + e];
        g_src[e] = s; g_dst[e] = d;
        atomicAdd(&g_deg[d], 1.0f);
    }
}

__global__ void k_dinv() {
    int n = blockIdx.x * blockDim.x + threadIdx.x;
    if (n < N_NODES) g_dinv[n] = 1.0f / sqrtf(g_deg[n] + 1.0f);
}

// pass 2: scatter pos (3-dim) with symmetric norm
__global__ void k_agg3(const float* __restrict__ pos) {
    int e = blockIdx.x * blockDim.x + threadIdx.x;
    if (e < N_EDGES) {
        int s = g_src[e], d = g_dst[e];
        float nm = g_dinv[s] * g_dinv[d];
        atomicAdd(&g_agg3[3 * d + 0], pos[3 * s + 0] * nm);
        atomicAdd(&g_agg3[3 * d + 1], pos[3 * s + 1] * nm);
        atomicAdd(&g_agg3[3 * d + 2], pos[3 * s + 2] * nm);
    }
}

// fused: h = leaky((agg3 + pos*dinv^2) @ W1 + b1); score = tanh((h.p1)/||p1||)
__global__ void k_score1(const float* __restrict__ pos, const float* __restrict__ W1,
                         const float* __restrict__ b1, const float* __restrict__ p1) {
    __shared__ float sW[192], sb[64], sp[64];
    for (int t = threadIdx.x; t < 192; t += blockDim.x) sW[t] = W1[t];
    for (int t = threadIdx.x; t < 64; t += blockDim.x) { sb[t] = b1[t]; sp[t] = p1[t]; }
    __syncthreads();
    int n = blockIdx.x * blockDim.x + threadIdx.x;
    if (n < N_NODES) {
        float di = g_dinv[n], di2 = di * di;
        float q0 = g_agg3[3 * n + 0] + pos[3 * n + 0] * di2;
        float q1 = g_agg3[3 * n + 1] + pos[3 * n + 1] * di2;
        float q2 = g_agg3[3 * n + 2] + pos[3 * n + 2] * di2;
        float s = 0.f;
        #pragma unroll 8
        for (int j = 0; j < 64; j++) {
            float h = q0 * sW[j] + q1 * sW[64 + j] + q2 * sW[128 + j] + sb[j];
            s += lrelu(h) * sp[j];
        }
        g_score1[n] = tanhf(s * g_invn1);
    }
}

// radix-select k-th largest: histogram pass
__global__ void k_hist(int pass) {
    __shared__ unsigned sh[256];
    if (threadIdx.x < 256) sh[threadIdx.x] = 0u;
    __syncthreads();
    unsigned pref = g_prefix;
    int hishift = 32 - 8 * pass;     // only used if pass>0
    int binshift = 24 - 8 * pass;
    int stride = gridDim.x * blockDim.x;
    for (int n = blockIdx.x * blockDim.x + threadIdx.x; n < N_NODES; n += stride) {
        unsigned u = f2u(g_score1[n]);
        if (pass == 0 || (u >> hishift) == pref)
            atomicAdd(&sh[(u >> binshift) & 255u], 1u);
    }
    __syncthreads();
    if (threadIdx.x < 256 && sh[threadIdx.x]) atomicAdd(&g_hist[threadIdx.x], sh[threadIdx.x]);
}

__global__ void k_scan() {
    // thread 0: pick bin containing the k-th largest, update prefix/krem;
    // all 256 threads then zero the histogram for the next pass.
    __shared__ unsigned cnt[256];
    cnt[threadIdx.x] = g_hist[threadIdx.x];
    __syncthreads();
    if (threadIdx.x == 0) {
        int krem = g_krem;
        unsigned cum = 0; int bin = 0;
        for (int b = 255; b >= 0; b--) {
            unsigned c = cnt[b];
            if (cum + c >= (unsigned)krem) { bin = b; break; }
            cum += c;
        }
        g_prefix = (g_prefix << 8) | (unsigned)bin;
        g_krem = krem - (int)cum;
    }
    g_hist[threadIdx.x] = 0u;
}

__global__ void k_compact() {
    int n = blockIdx.x * blockDim.x + threadIdx.x;
    if (n < N_NODES) {
        if (f2u(g_score1[n]) >= g_prefix) {
            int p = atomicAdd(&g_ccount, 1);
            g_cand[p] = n;
        }
    }
}

// rank candidates: (score desc, index asc) -> perm1 (== jax.lax.top_k order)
__global__ void k_rank1() {
    __shared__ unsigned su[8192];
    int C = g_ccount;
    int cc = (C < 8192) ? C : 8192;
    for (int j = threadIdx.x; j < cc; j += blockDim.x)
        su[j] = f2u(g_score1[g_cand[j]]);
    __syncthreads();
    int stride = gridDim.x * blockDim.x;
    for (int t = blockIdx.x * blockDim.x + threadIdx.x; t < C; t += stride) {
        int idx = g_cand[t];
        unsigned u = f2u(g_score1[idx]);
        int r = 0;
        for (int j = 0; j < C; j++) {
            unsigned uj = (j < cc) ? su[j] : f2u(g_score1[g_cand[j]]);
            if (uj > u) r++;
            else if (uj == u && j != t) { if (g_cand[j] < idx) r++; }
        }
        if (r < KP1) { g_perm1[r] = idx; g_psc1[r] = g_score1[idx]; }
    }
}

// recompute h for kept nodes, scale by score; build inverse mapping
__global__ void k_gather1(const float* __restrict__ pos, const float* __restrict__ W1,
                          const float* __restrict__ b1) {
    __shared__ float sW[192], sb[64];
    for (int t = threadIdx.x; t < 192; t += blockDim.x) sW[t] = W1[t];
    for (int t = threadIdx.x; t < 64; t += blockDim.x) sb[t] = b1[t];
    __syncthreads();
    int r = blockIdx.x;
    int j = threadIdx.x;         // 64 threads
    int n = g_perm1[r];
    float sc = g_psc1[r];
    float di = g_dinv[n], di2 = di * di;
    float q0 = g_agg3[3 * n + 0] + pos[3 * n + 0] * di2;
    float q1 = g_agg3[3 * n + 1] + pos[3 * n + 1] * di2;
    float q2 = g_agg3[3 * n + 2] + pos[3 * n + 2] * di2;
    float h = q0 * sW[j] + q1 * sW[64 + j] + q2 * sW[128 + j] + sb[j];
    g_x1p[r * 64 + j] = lrelu(h) * sc;
    if (j == 0) g_map[n] = r;
}

// keep only edges whose both endpoints survived pool1; accumulate new degree
__global__ void k_ecompact() {
    int e = blockIdx.x * blockDim.x + threadIdx.x;
    if (e < N_EDGES) {
        int ms = g_map[g_src[e]];
        int md = g_map[g_dst[e]];
        if (ms >= 0 && md >= 0) {
            int p = atomicAdd(&g_e2cnt, 1);
            g_e2s[p] = ms; g_e2d[p] = md;
            atomicAdd(&g_deg2[md], 1.0f);
        }
    }
}

__global__ void k_dinv2() {
    int n = blockIdx.x * blockDim.x + threadIdx.x;
    if (n < KP1) g_dinv2[n] = 1.0f / sqrtf(g_deg2[n]);
}

__global__ void k_self64() {
    int t = blockIdx.x * blockDim.x + threadIdx.x;
    if (t < KP1 * 64) {
        int n = t >> 6;
        float di = g_dinv2[n];
        g_agg64[t] = g_x1p[t] * di * di;
    }
}

__global__ void k_escat64() {
    int total = g_e2cnt * 64;
    int stride = gridDim.x * blockDim.x;
    for (int t = blockIdx.x * blockDim.x + threadIdx.x; t < total; t += stride) {
        int e = t >> 6, j = t & 63;
        int s = g_e2s[e], d = g_e2d[e];
        float nm = g_dinv2[s] * g_dinv2[d];
        atomicAdd(&g_agg64[d * 64 + j], g_x1p[s * 64 + j] * nm);
    }
}

// x2 = leaky(agg64 @ W2 + b2) : [4096,64]@[64,128]
__global__ void __launch_bounds__(128) k_gemm2(const float* __restrict__ W2,
                                               const float* __restrict__ b2) {
    __shared__ float sA[32 * 64];
    int row0 = blockIdx.x * 32;
    int c = threadIdx.x;
    for (int t = threadIdx.x; t < 32 * 64; t += 128) sA[t] = g_agg64[row0 * 64 + t];
    __syncthreads();
    float acc[32];
    float bb = b2[c];
    #pragma unroll
    for (int r = 0; r < 32; r++) acc[r] = bb;
    for (int k = 0; k < 64; k++) {
        float w = W2[k * 128 + c];
        #pragma unroll
        for (int r = 0; r < 32; r++) acc[r] += sA[r * 64 + k] * w;
    }
    #pragma unroll
    for (int r = 0; r < 32; r++) g_x2[(row0 + r) * 128 + c] = lrelu(acc[r]);
}

__global__ void k_self128() {
    int t = blockIdx.x * blockDim.x + threadIdx.x;
    if (t < KP1 * 128) {
        int n = t >> 7;
        float di = g_dinv2[n];
        g_agg128[t] = g_x2[t] * di * di;
    }
}

__global__ void k_escat128() {
    int total = g_e2cnt * 128;
    int stride = gridDim.x * blockDim.x;
    for (int t = blockIdx.x * blockDim.x + threadIdx.x; t < total; t += stride) {
        int e = t >> 7, j = t & 127;
        int s = g_e2s[e], d = g_e2d[e];
        float nm = g_dinv2[s] * g_dinv2[d];
        atomicAdd(&g_agg128[d * 128 + j], g_x2[s * 128 + j] * nm);
    }
}

// x3 = leaky(agg128 @ W3 + b3) : [4096,128]@[128,256]
__global__ void __launch_bounds__(256) k_gemm3(const float* __restrict__ W3,
                                               const float* __restrict__ b3) {
    __shared__ float sA[16 * 128];
    int row0 = blockIdx.x * 16;
    int c = threadIdx.x;
    for (int t = threadIdx.x; t < 16 * 128; t += 256) sA[t] = g_agg128[row0 * 128 + t];
    __syncthreads();
    float acc[16];
    float bb = b3[c];
    #pragma unroll
    for (int r = 0; r < 16; r++) acc[r] = bb;
    for (int k = 0; k < 128; k++) {
        float w = W3[k * 256 + c];
        #pragma unroll
        for (int r = 0; r < 16; r++) acc[r] += sA[r * 128 + k] * w;
    }
    #pragma unroll
    for (int r = 0; r < 16; r++) g_x3[(row0 + r) * 256 + c] = lrelu(acc[r]);
}

// score2 = tanh((x3 @ p2)/||p2||): one warp per node
__global__ void k_score2(const float* __restrict__ p2) {
    __shared__ float sp[256];
    for (int t = threadIdx.x; t < 256; t += blockDim.x) sp[t] = p2[t];
    __syncthreads();
    int gw = (blockIdx.x * blockDim.x + threadIdx.x) >> 5;
    int lane = threadIdx.x & 31;
    if (gw < KP1) {
        float s = 0.f;
        #pragma unroll
        for (int j = lane; j < 256; j += 32) s += g_x3[gw * 256 + j] * sp[j];
        #pragma unroll
        for (int off = 16; off > 0; off >>= 1) s += __shfl_xor_sync(0xFFFFFFFFu, s, off);
        if (lane == 0) g_score2[gw] = tanhf(s * g_invn2);
    }
}

// direct O(N^2) ranking for pool2 (4096 -> 256)
__global__ void k_rank2() {
    __shared__ float ss[KP1];
    for (int j = threadIdx.x; j < KP1; j += blockDim.x) ss[j] = g_score2[j];
    __syncthreads();
    int t = blockIdx.x * blockDim.x + threadIdx.x;   // exactly KP1 threads
    float s = ss[t];
    int r = 0;
    for (int j = 0; j < KP1; j++) {
        float v = ss[j];
        if (v > s) r++;
        else if (v == s && j < t) r++;
    }
    if (r < KP2) { g_perm2[r] = t; g_sc2[r] = s; }
}

// v[f*256 + n] = x3[perm2[n]][f] * sc2[n]  (== x.T.reshape(-1)); also init out=fcb
__global__ void k_build_v(const float* __restrict__ fcb, float* __restrict__ out) {
    int t = blockIdx.x * blockDim.x + threadIdx.x;
    if (t < KP2 * 256) {
        int f = t >> 8, n = t & 255;
        g_v[t] = g_x3[g_perm2[n] * 256 + f] * g_sc2[n];
    }
    if (t < 512) out[t] = fcb[t];
}

// out += v @ fcW : [65536]@[65536,512]
__global__ void __launch_bounds__(512) k_fc(const float* __restrict__ fcW,
                                            float* __restrict__ out) {
    __shared__ float sv[256];
    int o = threadIdx.x;
    int i0 = blockIdx.x * 256;
    for (int t = threadIdx.x; t < 256; t += 512) sv[t] = g_v[i0 + t];
    __syncthreads();
    float acc = 0.f;
    #pragma unroll 8
    for (int k = 0; k < 256; k++) acc += sv[k] * fcW[(size_t)(i0 + k) * 512 + o];
    atomicAdd(&out[o], acc);
}

// ---------------- launch ----------------
extern "C" void kernel_launch(void* const* d_in, const int* in_sizes, int n_in,
                              void* d_out, int out_size) {
    const float* pos = (const float*)d_in[0];
    const int*   ei  = (const int*)d_in[1];     // int32 (JAX default, no x64)
    const float* W1 = (const float*)d_in[2];
    const float* b1 = (const float*)d_in[3];
    const float* W2 = (const float*)d_in[4];
    const float* b2 = (const float*)d_in[5];
    const float* W3 = (const float*)d_in[6];
    const float* b3 = (const float*)d_in[7];
    const float* p1 = (const float*)d_in[8];
    const float* p2 = (const float*)d_in[9];
    const float* fcW = (const float*)d_in[10];
    const float* fcb = (const float*)d_in[11];
    float* out = (float*)d_out;

    const int EB = (N_EDGES + 255) / 256;
    const int NB = (N_NODES + 255) / 256;

    k_init<<<1172, 256>>>(p1, p2);
    k_edge_deg<<<EB, 256>>>(ei);
    k_dinv<<<NB, 256>>>();
    k_agg3<<<EB, 256>>>(pos);
    k_score1<<<NB, 256>>>(pos, W1, b1, p1);
    for (int p = 0; p < 4; p++) {
        k_hist<<<256, 256>>>(p);
        k_scan<<<1, 256>>>();
    }
    k_compact<<<NB, 256>>>();
    k_rank1<<<32, 256>>>();
    k_gather1<<<KP1, 64>>>(pos, W1, b1);
    k_ecompact<<<EB, 256>>>();
    k_dinv2<<<16, 256>>>();
    k_self64<<<1024, 256>>>();
    k_escat64<<<256, 256>>>();
    k_gemm2<<<128, 128>>>(W2, b2);
    k_self128<<<2048, 256>>>();
    k_escat128<<<256, 256>>>();
    k_gemm3<<<256, 256>>>(W3, b3);
    k_score2<<<512, 256>>>(p2);
    k_rank2<<<16, 256>>>();
    k_build_v<<<256, 256>>>(fcb, out);
    k_fc<<<256, 512>>>(fcW, out);
}

// round 4
// speedup vs baseline: 1.0068x; 1.0068x over previous
#include <cuda_runtime.h>
#include <math.h>

#define N_NODES 100000
#define N_EDGES 1200000
#define KP1 4096
#define KP2 256
#define NEG 0.01f
#define RCAP 12288   // rank1 smem key capacity (48 KB)

// ---------------- device scratch (static; no runtime allocation) ----------------
__device__ int    g_src[N_EDGES], g_dst[N_EDGES];
__device__ float  g_deg[N_NODES];
__device__ float4 g_pos4[N_NODES];
__device__ float4 g_agg4[N_NODES];
__device__ float  g_score1[N_NODES];
__device__ int    g_map[N_NODES];
__device__ unsigned g_hist16[65536];
__device__ unsigned g_thresh;
__device__ int    g_ccount;
__device__ int    g_cand[N_NODES];
__device__ int    g_perm1[KP1];
__device__ float  g_psc1[KP1];
__device__ float  g_x1p[KP1 * 64];
__device__ int    g_e2s[N_EDGES], g_e2d[N_EDGES];
__device__ int    g_e2cnt;
__device__ float  g_deg2[KP1];
__device__ float  g_agg64[KP1 * 64];
__device__ float  g_x2[KP1 * 128];
__device__ float  g_agg128[KP1 * 128];
__device__ float  g_x3[KP1 * 256];
__device__ float  g_score2[KP1];
__device__ int    g_perm2[KP2];
__device__ float  g_sc2[KP2];
__device__ float  g_invn1, g_invn2;

__device__ __forceinline__ unsigned f2u(float f) {
    unsigned u = __float_as_uint(f);
    return (u & 0x80000000u) ? ~u : (u | 0x80000000u);
}
__device__ __forceinline__ float lrelu(float h) { return (h < 0.f) ? NEG * h : h; }

// ---------------- kernels ----------------

// init everything (idempotent per graph replay); copy pos->float4; out = fcb
__global__ void k_init(const float* __restrict__ pos,
                       const float* __restrict__ p1, const float* __restrict__ p2,
                       const float* __restrict__ fcb, float* __restrict__ out) {
    int i = blockIdx.x * blockDim.x + threadIdx.x;
    int stride = gridDim.x * blockDim.x;
    for (int t = i; t < N_NODES; t += stride) {
        g_deg[t] = 0.f; g_map[t] = -1;
        g_pos4[t] = make_float4(pos[3 * t], pos[3 * t + 1], pos[3 * t + 2], 0.f);
        g_agg4[t] = make_float4(0.f, 0.f, 0.f, 0.f);
    }
    for (int t = i; t < 65536; t += stride) g_hist16[t] = 0u;
    for (int t = i; t < KP1 * 64; t += stride) g_agg64[t] = 0.f;
    for (int t = i; t < KP1 * 128; t += stride) g_agg128[t] = 0.f;
    for (int t = i; t < KP1; t += stride) g_deg2[t] = 1.0f;
    if (i < 512) out[i] = fcb[i];
    if (i == 0) {
        g_ccount = 0; g_e2cnt = 0;
        float s = 0.f;
        for (int j = 0; j < 64; j++) s += p1[j] * p1[j];
        g_invn1 = 1.0f / sqrtf(s);
        s = 0.f;
        for (int j = 0; j < 256; j++) s += p2[j] * p2[j];
        g_invn2 = 1.0f / sqrtf(s);
    }
}

// pass 1 over edges: copy int32 indices + in-degree
__global__ void k_edge_deg(const int* __restrict__ ei) {
    int e = blockIdx.x * blockDim.x + threadIdx.x;
    if (e < N_EDGES) {
        int s = ei[e];
        int d = ei[N_EDGES + e];
        g_src[e] = s; g_dst[e] = d;
        atomicAdd(&g_deg[d], 1.0f);
    }
}

// pass 2: scatter pos (float4 vector atomic) with symmetric norm (rsqrt inline)
__global__ void k_agg3() {
    int e = blockIdx.x * blockDim.x + threadIdx.x;
    if (e < N_EDGES) {
        int s = g_src[e], d = g_dst[e];
        float nm = rsqrtf(g_deg[s] + 1.0f) * rsqrtf(g_deg[d] + 1.0f);
        float4 p = g_pos4[s];
        atomicAdd(&g_agg4[d], make_float4(p.x * nm, p.y * nm, p.z * nm, 0.f));
    }
}

// fused: h = leaky((agg + pos*dinv^2) @ W1 + b1); score = tanh((h.p1)/||p1||); hist16
__global__ void k_score1(const float* __restrict__ W1, const float* __restrict__ b1,
                         const float* __restrict__ p1) {
    __shared__ float sW[192], sb[64], sp[64];
    for (int t = threadIdx.x; t < 192; t += blockDim.x) sW[t] = W1[t];
    for (int t = threadIdx.x; t < 64; t += blockDim.x) { sb[t] = b1[t]; sp[t] = p1[t]; }
    __syncthreads();
    int n = blockIdx.x * blockDim.x + threadIdx.x;
    if (n < N_NODES) {
        float di = rsqrtf(g_deg[n] + 1.0f), di2 = di * di;
        float4 a = g_agg4[n];
        float4 p = g_pos4[n];
        float q0 = a.x + p.x * di2;
        float q1 = a.y + p.y * di2;
        float q2 = a.z + p.z * di2;
        float s = 0.f;
        #pragma unroll 8
        for (int j = 0; j < 64; j++) {
            float h = q0 * sW[j] + q1 * sW[64 + j] + q2 * sW[128 + j] + sb[j];
            s += lrelu(h) * sp[j];
        }
        float sc = tanhf(s * g_invn1);
        g_score1[n] = sc;
        atomicAdd(&g_hist16[f2u(sc) >> 16], 1u);
    }
}

// find 16-bit threshold bin of the KP1-th largest score (single block)
__global__ void k_scan16() {
    __shared__ unsigned P[1024];
    int t = threadIdx.x;
    unsigned s = 0;
    #pragma unroll 8
    for (int i = 0; i < 64; i++) s += g_hist16[t * 64 + i];
    P[t] = s;
    __syncthreads();
    if (t == 0) {
        unsigned cum = 0; int c = 1023;
        for (; c > 0; c--) {
            if (cum + P[c] >= (unsigned)KP1) break;
            cum += P[c];
        }
        unsigned th = 0;
        for (int b = c * 64 + 63; b >= c * 64; b--) {
            cum += g_hist16[b];
            if (cum >= (unsigned)KP1) { th = (unsigned)b; break; }
        }
        g_thresh = th;
    }
}

__global__ void k_compact() {
    int n = blockIdx.x * blockDim.x + threadIdx.x;
    if (n < N_NODES) {
        if ((f2u(g_score1[n]) >> 16) >= g_thresh) {
            int p = atomicAdd(&g_ccount, 1);
            g_cand[p] = n;
        }
    }
}

// rank candidates: (score desc, index asc) -> perm1 (== jax.lax.top_k order)
__global__ void k_rank1() {
    __shared__ unsigned su[RCAP];
    int C = g_ccount;
    int cc = (C < RCAP) ? C : RCAP;
    for (int j = threadIdx.x; j < cc; j += blockDim.x)
        su[j] = f2u(g_score1[g_cand[j]]);
    __syncthreads();
    int stride = gridDim.x * blockDim.x;
    for (int t = blockIdx.x * blockDim.x + threadIdx.x; t < C; t += stride) {
        int idx = g_cand[t];
        unsigned u = f2u(g_score1[idx]);
        int r = 0;
        for (int j = 0; j < C; j++) {
            unsigned uj = (j < cc) ? su[j] : f2u(g_score1[g_cand[j]]);
            if (uj > u) r++;
            else if (uj == u && j != t) { if (g_cand[j] < idx) r++; }
        }
        if (r < KP1) { g_perm1[r] = idx; g_psc1[r] = g_score1[idx]; }
    }
}

// recompute h for kept nodes, scale by score; build inverse mapping
__global__ void k_gather1(const float* __restrict__ W1, const float* __restrict__ b1) {
    __shared__ float sW[192], sb[64];
    for (int t = threadIdx.x; t < 192; t += blockDim.x) sW[t] = W1[t];
    for (int t = threadIdx.x; t < 64; t += blockDim.x) sb[t] = b1[t];
    __syncthreads();
    int r = blockIdx.x;
    int j = threadIdx.x;         // 64 threads
    int n = g_perm1[r];
    float sc = g_psc1[r];
    float di = rsqrtf(g_deg[n] + 1.0f), di2 = di * di;
    float4 a = g_agg4[n];
    float4 p = g_pos4[n];
    float q0 = a.x + p.x * di2;
    float q1 = a.y + p.y * di2;
    float q2 = a.z + p.z * di2;
    float h = q0 * sW[j] + q1 * sW[64 + j] + q2 * sW[128 + j] + sb[j];
    g_x1p[r * 64 + j] = lrelu(h) * sc;
    if (j == 0) g_map[n] = r;
}

// keep only edges whose both endpoints survived pool1; accumulate new degree
__global__ void k_ecompact() {
    int e = blockIdx.x * blockDim.x + threadIdx.x;
    if (e < N_EDGES) {
        int ms = g_map[g_src[e]];
        int md = g_map[g_dst[e]];
        if (ms >= 0 && md >= 0) {
            int p = atomicAdd(&g_e2cnt, 1);
            g_e2s[p] = ms; g_e2d[p] = md;
            atomicAdd(&g_deg2[md], 1.0f);
        }
    }
}

__global__ void k_escat64() {
    int total = g_e2cnt * 64;
    int stride = gridDim.x * blockDim.x;
    for (int t = blockIdx.x * blockDim.x + threadIdx.x; t < total; t += stride) {
        int e = t >> 6, j = t & 63;
        int s = g_e2s[e], d = g_e2d[e];
        float nm = rsqrtf(g_deg2[s]) * rsqrtf(g_deg2[d]);
        atomicAdd(&g_agg64[d * 64 + j], g_x1p[s * 64 + j] * nm);
    }
}

// x2 = leaky((agg64 + x1p*dinv2^2) @ W2 + b2) : [4096,64]@[64,128], self-term fused
__global__ void __launch_bounds__(128) k_gemm2(const float* __restrict__ W2,
                                               const float* __restrict__ b2) {
    __shared__ float sA[32 * 64];
    int row0 = blockIdx.x * 32;
    int c = threadIdx.x;
    for (int t = threadIdx.x; t < 32 * 64; t += 128) {
        int row = row0 + (t >> 6);
        float di = rsqrtf(g_deg2[row]);
        sA[t] = g_agg64[row0 * 64 + t] + g_x1p[row0 * 64 + t] * di * di;
    }
    __syncthreads();
    float acc[32];
    float bb = b2[c];
    #pragma unroll
    for (int r = 0; r < 32; r++) acc[r] = bb;
    for (int k = 0; k < 64; k++) {
        float w = W2[k * 128 + c];
        #pragma unroll
        for (int r = 0; r < 32; r++) acc[r] += sA[r * 64 + k] * w;
    }
    #pragma unroll
    for (int r = 0; r < 32; r++) g_x2[(row0 + r) * 128 + c] = lrelu(acc[r]);
}

__global__ void k_escat128() {
    int total = g_e2cnt * 128;
    int stride = gridDim.x * blockDim.x;
    for (int t = blockIdx.x * blockDim.x + threadIdx.x; t < total; t += stride) {
        int e = t >> 7, j = t & 127;
        int s = g_e2s[e], d = g_e2d[e];
        float nm = rsqrtf(g_deg2[s]) * rsqrtf(g_deg2[d]);
        atomicAdd(&g_agg128[d * 128 + j], g_x2[s * 128 + j] * nm);
    }
}

// x3 = leaky((agg128 + x2*dinv2^2) @ W3 + b3) : [4096,128]@[128,256], self fused
__global__ void __launch_bounds__(256) k_gemm3(const float* __restrict__ W3,
                                               const float* __restrict__ b3) {
    __shared__ float sA[16 * 128];
    int row0 = blockIdx.x * 16;
    int c = threadIdx.x;
    for (int t = threadIdx.x; t < 16 * 128; t += 256) {
        int row = row0 + (t >> 7);
        float di = rsqrtf(g_deg2[row]);
        sA[t] = g_agg128[row0 * 128 + t] + g_x2[row0 * 128 + t] * di * di;
    }
    __syncthreads();
    float acc[16];
    float bb = b3[c];
    #pragma unroll
    for (int r = 0; r < 16; r++) acc[r] = bb;
    for (int k = 0; k < 128; k++) {
        float w = W3[k * 256 + c];
        #pragma unroll
        for (int r = 0; r < 16; r++) acc[r] += sA[r * 128 + k] * w;
    }
    #pragma unroll
    for (int r = 0; r < 16; r++) g_x3[(row0 + r) * 256 + c] = lrelu(acc[r]);
}

// score2 = tanh((x3 @ p2)/||p2||): one warp per node
__global__ void k_score2(const float* __restrict__ p2) {
    __shared__ float sp[256];
    for (int t = threadIdx.x; t < 256; t += blockDim.x) sp[t] = p2[t];
    __syncthreads();
    int gw = (blockIdx.x * blockDim.x + threadIdx.x) >> 5;
    int lane = threadIdx.x & 31;
    if (gw < KP1) {
        float s = 0.f;
        #pragma unroll
        for (int j = lane; j < 256; j += 32) s += g_x3[gw * 256 + j] * sp[j];
        #pragma unroll
        for (int off = 16; off > 0; off >>= 1) s += __shfl_xor_sync(0xFFFFFFFFu, s, off);
        if (lane == 0) g_score2[gw] = tanhf(s * g_invn2);
    }
}

// direct O(N^2) ranking for pool2 (4096 -> 256)
__global__ void k_rank2() {
    __shared__ float ss[KP1];
    for (int j = threadIdx.x; j < KP1; j += blockDim.x) ss[j] = g_score2[j];
    __syncthreads();
    int t = blockIdx.x * blockDim.x + threadIdx.x;   // exactly KP1 threads
    float s = ss[t];
    int r = 0;
    for (int j = 0; j < KP1; j++) {
        float v = ss[j];
        if (v > s) r++;
        else if (v == s && j < t) r++;
    }
    if (r < KP2) { g_perm2[r] = t; g_sc2[r] = s; }
}

// out += v @ fcW with v built on the fly: v[f*256+n] = x3[perm2[n]][f]*sc2[n]
// 512 blocks; block b covers v-range [b*128, b*128+128) => f = b>>1, n = (b&1)*128 ..
__global__ void __launch_bounds__(256) k_fc(const float* __restrict__ fcW,
                                            float* __restrict__ out) {
    __shared__ float sv[128];
    __shared__ float4 sacc[128];
    int b = blockIdx.x;
    int f = b >> 1;
    int n0 = (b & 1) << 7;
    int t = threadIdx.x;
    if (t < 128) {
        int n = n0 + t;
        sv[t] = g_x3[g_perm2[n] * 256 + f] * g_sc2[n];
    }
    __syncthreads();
    int sub = t >> 7, o4 = t & 127;
    const float4* fw = (const float4*)fcW;
    float4 acc = make_float4(0.f, 0.f, 0.f, 0.f);
    size_t base = ((size_t)b * 128 + (size_t)sub * 64) * 128 + o4;
    #pragma unroll 8
    for (int j = 0; j < 64; j++) {
        float s = sv[sub * 64 + j];
        float4 w = fw[base + (size_t)j * 128];
        acc.x += s * w.x; acc.y += s * w.y; acc.z += s * w.z; acc.w += s * w.w;
    }
    if (sub == 1) sacc[o4] = acc;
    __syncthreads();
    if (sub == 0) {
        float4 o = sacc[o4];
        acc.x += o.x; acc.y += o.y; acc.z += o.z; acc.w += o.w;
        atomicAdd(((float4*)out) + o4, acc);
    }
}

// ---------------- launch ----------------
extern "C" void kernel_launch(void* const* d_in, const int* in_sizes, int n_in,
                              void* d_out, int out_size) {
    const float* pos = (const float*)d_in[0];
    const int*   ei  = (const int*)d_in[1];     // int32 (JAX default, no x64)
    const float* W1 = (const float*)d_in[2];
    const float* b1 = (const float*)d_in[3];
    const float* W2 = (const float*)d_in[4];
    const float* b2 = (const float*)d_in[5];
    const float* W3 = (const float*)d_in[6];
    const float* b3 = (const float*)d_in[7];
    const float* p1 = (const float*)d_in[8];
    const float* p2 = (const float*)d_in[9];
    const float* fcW = (const float*)d_in[10];
    const float* fcb = (const float*)d_in[11];
    float* out = (float*)d_out;

    const int EB = (N_EDGES + 255) / 256;
    const int NB = (N_NODES + 255) / 256;

    k_init<<<2048, 256>>>(pos, p1, p2, fcb, out);
    k_edge_deg<<<EB, 256>>>(ei);
    k_agg3<<<EB, 256>>>();
    k_score1<<<NB, 256>>>(W1, b1, p1);
    k_scan16<<<1, 1024>>>();
    k_compact<<<NB, 256>>>();
    k_rank1<<<32, 256>>>();
    k_gather1<<<KP1, 64>>>(W1, b1);
    k_ecompact<<<EB, 256>>>();
    k_escat64<<<256, 256>>>();
    k_gemm2<<<128, 128>>>(W2, b2);
    k_escat128<<<256, 256>>>();
    k_gemm3<<<256, 256>>>(W3, b3);
    k_score2<<<512, 256>>>(p2);
    k_rank2<<<16, 256>>>();
    k_fc<<<512, 256>>>(fcW, out);
}

// round 5
// speedup vs baseline: 1.0173x; 1.0105x over previous
#include <cuda_runtime.h>
#include <math.h>

#define N_NODES 100000
#define N_EDGES 1200000
#define KP1 4096
#define KP2 256
#define NEG 0.01f
#define RCAP 12288   // rank1 smem key capacity (48 KB)

// ---------------- device scratch (static; no runtime allocation) ----------------
__device__ int    g_src[N_EDGES], g_dst[N_EDGES];
__device__ float  g_deg[N_NODES];
__device__ float4 g_pos4[N_NODES];
__device__ float4 g_agg4[N_NODES];
__device__ float  g_score1[N_NODES];
__device__ int    g_map[N_NODES];
__device__ unsigned g_hist16[65536];
__device__ unsigned g_thresh;
__device__ int    g_ccount;
__device__ int    g_cand[N_NODES];
__device__ int    g_perm1[KP1];
__device__ float  g_psc1[KP1];
__device__ float  g_x1p[KP1 * 64];
__device__ int    g_e2s[N_EDGES], g_e2d[N_EDGES];
__device__ int    g_e2cnt;
__device__ float  g_deg2[KP1];
__device__ float  g_agg64[KP1 * 64];
__device__ float  g_x2[KP1 * 128];
__device__ float  g_agg128[KP1 * 128];
__device__ float  g_x3[KP1 * 256];
__device__ float  g_score2[KP1];
__device__ int    g_perm2[KP2];
__device__ float  g_sc2[KP2];
__device__ float  g_invn1, g_invn2;
__device__ float  g_sink;          // probe sink; never read, never affects output

__device__ __forceinline__ unsigned f2u(float f) {
    unsigned u = __float_as_uint(f);
    return (u & 0x80000000u) ? ~u : (u | 0x80000000u);
}
__device__ __forceinline__ float lrelu(float h) { return (h < 0.f) ? NEG * h : h; }

// ---------------- kernels ----------------

// init everything (idempotent per graph replay); copy pos->float4; out = fcb
__global__ void k_init(const float* __restrict__ pos,
                       const float* __restrict__ p1, const float* __restrict__ p2,
                       const float* __restrict__ fcb, float* __restrict__ out) {
    int i = blockIdx.x * blockDim.x + threadIdx.x;
    int stride = gridDim.x * blockDim.x;
    for (int t = i; t < N_NODES; t += stride) {
        g_deg[t] = 0.f; g_map[t] = -1;
        g_pos4[t] = make_float4(pos[3 * t], pos[3 * t + 1], pos[3 * t + 2], 0.f);
        g_agg4[t] = make_float4(0.f, 0.f, 0.f, 0.f);
    }
    for (int t = i; t < 65536; t += stride) g_hist16[t] = 0u;
    for (int t = i; t < KP1 * 64; t += stride) g_agg64[t] = 0.f;
    for (int t = i; t < KP1 * 128; t += stride) g_agg128[t] = 0.f;
    for (int t = i; t < KP1; t += stride) g_deg2[t] = 1.0f;
    if (i < 512) out[i] = fcb[i];
    if (i == 0) {
        g_ccount = 0; g_e2cnt = 0;
        float s = 0.f;
        for (int j = 0; j < 64; j++) s += p1[j] * p1[j];
        g_invn1 = 1.0f / sqrtf(s);
        s = 0.f;
        for (int j = 0; j < 256; j++) s += p2[j] * p2[j];
        g_invn2 = 1.0f / sqrtf(s);
    }
}

// pass 1 over edges: copy int32 indices + in-degree
__global__ void k_edge_deg(const int* __restrict__ ei) {
    int e = blockIdx.x * blockDim.x + threadIdx.x;
    if (e < N_EDGES) {
        int s = ei[e];
        int d = ei[N_EDGES + e];
        g_src[e] = s; g_dst[e] = d;
        atomicAdd(&g_deg[d], 1.0f);
    }
}

// pass 2: scatter pos (float4 vector atomic) with symmetric norm (rsqrt inline)
__global__ void k_agg3() {
    int e = blockIdx.x * blockDim.x + threadIdx.x;
    if (e < N_EDGES) {
        int s = g_src[e], d = g_dst[e];
        float nm = rsqrtf(g_deg[s] + 1.0f) * rsqrtf(g_deg[d] + 1.0f);
        float4 p = g_pos4[s];
        atomicAdd(&g_agg4[d], make_float4(p.x * nm, p.y * nm, p.z * nm, 0.f));
    }
}

// DIAGNOSTIC (launch slot #4 -> gets profiled by ncu): pure streaming sweep of
// fcW with EXACTLY k_fc's access pattern. Result goes to a write-only sink.
__global__ void __launch_bounds__(256) k_probe(const float* __restrict__ fcW) {
    const float4* fw = (const float4*)fcW;
    int b = blockIdx.x;
    int t = threadIdx.x;
    int sub = t >> 7, o4 = t & 127;
    size_t base = ((size_t)b * 128 + (size_t)sub * 64) * 128 + o4;
    float4 acc = make_float4(0.f, 0.f, 0.f, 0.f);
    #pragma unroll 16
    for (int j = 0; j < 64; j++) {
        float4 w = __ldcs(&fw[base + (size_t)j * 128]);
        acc.x += w.x; acc.y += w.y; acc.z += w.z; acc.w += w.w;
    }
    float s = acc.x + acc.y + acc.z + acc.w;
    #pragma unroll
    for (int off = 16; off > 0; off >>= 1) s += __shfl_xor_sync(0xFFFFFFFFu, s, off);
    if ((t & 31) == 0) atomicAdd(&g_sink, s);
}

// fused: h = leaky((agg + pos*dinv^2) @ W1 + b1); score = tanh((h.p1)/||p1||); hist16
__global__ void k_score1(const float* __restrict__ W1, const float* __restrict__ b1,
                         const float* __restrict__ p1) {
    __shared__ float sW[192], sb[64], sp[64];
    for (int t = threadIdx.x; t < 192; t += blockDim.x) sW[t] = W1[t];
    for (int t = threadIdx.x; t < 64; t += blockDim.x) { sb[t] = b1[t]; sp[t] = p1[t]; }
    __syncthreads();
    int n = blockIdx.x * blockDim.x + threadIdx.x;
    if (n < N_NODES) {
        float di = rsqrtf(g_deg[n] + 1.0f), di2 = di * di;
        float4 a = g_agg4[n];
        float4 p = g_pos4[n];
        float q0 = a.x + p.x * di2;
        float q1 = a.y + p.y * di2;
        float q2 = a.z + p.z * di2;
        float s = 0.f;
        #pragma unroll 8
        for (int j = 0; j < 64; j++) {
            float h = q0 * sW[j] + q1 * sW[64 + j] + q2 * sW[128 + j] + sb[j];
            s += lrelu(h) * sp[j];
        }
        float sc = tanhf(s * g_invn1);
        g_score1[n] = sc;
        atomicAdd(&g_hist16[f2u(sc) >> 16], 1u);
    }
}

// find 16-bit threshold bin of the KP1-th largest score (single block)
__global__ void k_scan16() {
    __shared__ unsigned P[1024];
    int t = threadIdx.x;
    unsigned s = 0;
    #pragma unroll 8
    for (int i = 0; i < 64; i++) s += g_hist16[t * 64 + i];
    P[t] = s;
    __syncthreads();
    if (t == 0) {
        unsigned cum = 0; int c = 1023;
        for (; c > 0; c--) {
            if (cum + P[c] >= (unsigned)KP1) break;
            cum += P[c];
        }
        unsigned th = 0;
        for (int b = c * 64 + 63; b >= c * 64; b--) {
            cum += g_hist16[b];
            if (cum >= (unsigned)KP1) { th = (unsigned)b; break; }
        }
        g_thresh = th;
    }
}

__global__ void k_compact() {
    int n = blockIdx.x * blockDim.x + threadIdx.x;
    if (n < N_NODES) {
        if ((f2u(g_score1[n]) >> 16) >= g_thresh) {
            int p = atomicAdd(&g_ccount, 1);
            g_cand[p] = n;
        }
    }
}

// rank candidates: (score desc, index asc) -> perm1 (== jax.lax.top_k order)
__global__ void k_rank1() {
    __shared__ unsigned su[RCAP];
    int C = g_ccount;
    int cc = (C < RCAP) ? C : RCAP;
    for (int j = threadIdx.x; j < cc; j += blockDim.x)
        su[j] = f2u(g_score1[g_cand[j]]);
    __syncthreads();
    int stride = gridDim.x * blockDim.x;
    for (int t = blockIdx.x * blockDim.x + threadIdx.x; t < C; t += stride) {
        int idx = g_cand[t];
        unsigned u = f2u(g_score1[idx]);
        int r = 0;
        for (int j = 0; j < C; j++) {
            unsigned uj = (j < cc) ? su[j] : f2u(g_score1[g_cand[j]]);
            if (uj > u) r++;
            else if (uj == u && j != t) { if (g_cand[j] < idx) r++; }
        }
        if (r < KP1) { g_perm1[r] = idx; g_psc1[r] = g_score1[idx]; }
    }
}

// recompute h for kept nodes, scale by score; build inverse mapping
__global__ void k_gather1(const float* __restrict__ W1, const float* __restrict__ b1) {
    __shared__ float sW[192], sb[64];
    for (int t = threadIdx.x; t < 192; t += blockDim.x) sW[t] = W1[t];
    for (int t = threadIdx.x; t < 64; t += blockDim.x) sb[t] = b1[t];
    __syncthreads();
    int r = blockIdx.x;
    int j = threadIdx.x;         // 64 threads
    int n = g_perm1[r];
    float sc = g_psc1[r];
    float di = rsqrtf(g_deg[n] + 1.0f), di2 = di * di;
    float4 a = g_agg4[n];
    float4 p = g_pos4[n];
    float q0 = a.x + p.x * di2;
    float q1 = a.y + p.y * di2;
    float q2 = a.z + p.z * di2;
    float h = q0 * sW[j] + q1 * sW[64 + j] + q2 * sW[128 + j] + sb[j];
    g_x1p[r * 64 + j] = lrelu(h) * sc;
    if (j == 0) g_map[n] = r;
}

// keep only edges whose both endpoints survived pool1; accumulate new degree
__global__ void k_ecompact() {
    int e = blockIdx.x * blockDim.x + threadIdx.x;
    if (e < N_EDGES) {
        int ms = g_map[g_src[e]];
        int md = g_map[g_dst[e]];
        if (ms >= 0 && md >= 0) {
            int p = atomicAdd(&g_e2cnt, 1);
            g_e2s[p] = ms; g_e2d[p] = md;
            atomicAdd(&g_deg2[md], 1.0f);
        }
    }
}

__global__ void k_escat64() {
    int total = g_e2cnt * 64;
    int stride = gridDim.x * blockDim.x;
    for (int t = blockIdx.x * blockDim.x + threadIdx.x; t < total; t += stride) {
        int e = t >> 6, j = t & 63;
        int s = g_e2s[e], d = g_e2d[e];
        float nm = rsqrtf(g_deg2[s]) * rsqrtf(g_deg2[d]);
        atomicAdd(&g_agg64[d * 64 + j], g_x1p[s * 64 + j] * nm);
    }
}

// x2 = leaky((agg64 + x1p*dinv2^2) @ W2 + b2) : [4096,64]@[64,128], self-term fused
__global__ void __launch_bounds__(128) k_gemm2(const float* __restrict__ W2,
                                               const float* __restrict__ b2) {
    __shared__ float sA[32 * 64];
    int row0 = blockIdx.x * 32;
    int c = threadIdx.x;
    for (int t = threadIdx.x; t < 32 * 64; t += 128) {
        int row = row0 + (t >> 6);
        float di = rsqrtf(g_deg2[row]);
        sA[t] = g_agg64[row0 * 64 + t] + g_x1p[row0 * 64 + t] * di * di;
    }
    __syncthreads();
    float acc[32];
    float bb = b2[c];
    #pragma unroll
    for (int r = 0; r < 32; r++) acc[r] = bb;
    for (int k = 0; k < 64; k++) {
        float w = W2[k * 128 + c];
        #pragma unroll
        for (int r = 0; r < 32; r++) acc[r] += sA[r * 64 + k] * w;
    }
    #pragma unroll
    for (int r = 0; r < 32; r++) g_x2[(row0 + r) * 128 + c] = lrelu(acc[r]);
}

__global__ void k_escat128() {
    int total = g_e2cnt * 128;
    int stride = gridDim.x * blockDim.x;
    for (int t = blockIdx.x * blockDim.x + threadIdx.x; t < total; t += stride) {
        int e = t >> 7, j = t & 127;
        int s = g_e2s[e], d = g_e2d[e];
        float nm = rsqrtf(g_deg2[s]) * rsqrtf(g_deg2[d]);
        atomicAdd(&g_agg128[d * 128 + j], g_x2[s * 128 + j] * nm);
    }
}

// x3 = leaky((agg128 + x2*dinv2^2) @ W3 + b3) : [4096,128]@[128,256], self fused
__global__ void __launch_bounds__(256) k_gemm3(const float* __restrict__ W3,
                                               const float* __restrict__ b3) {
    __shared__ float sA[16 * 128];
    int row0 = blockIdx.x * 16;
    int c = threadIdx.x;
    for (int t = threadIdx.x; t < 16 * 128; t += 256) {
        int row = row0 + (t >> 7);
        float di = rsqrtf(g_deg2[row]);
        sA[t] = g_agg128[row0 * 128 + t] + g_x2[row0 * 128 + t] * di * di;
    }
    __syncthreads();
    float acc[16];
    float bb = b3[c];
    #pragma unroll
    for (int r = 0; r < 16; r++) acc[r] = bb;
    for (int k = 0; k < 128; k++) {
        float w = W3[k * 256 + c];
        #pragma unroll
        for (int r = 0; r < 16; r++) acc[r] += sA[r * 128 + k] * w;
    }
    #pragma unroll
    for (int r = 0; r < 16; r++) g_x3[(row0 + r) * 256 + c] = lrelu(acc[r]);
}

// score2 = tanh((x3 @ p2)/||p2||): one warp per node
__global__ void k_score2(const float* __restrict__ p2) {
    __shared__ float sp[256];
    for (int t = threadIdx.x; t < 256; t += blockDim.x) sp[t] = p2[t];
    __syncthreads();
    int gw = (blockIdx.x * blockDim.x + threadIdx.x) >> 5;
    int lane = threadIdx.x & 31;
    if (gw < KP1) {
        float s = 0.f;
        #pragma unroll
        for (int j = lane; j < 256; j += 32) s += g_x3[gw * 256 + j] * sp[j];
        #pragma unroll
        for (int off = 16; off > 0; off >>= 1) s += __shfl_xor_sync(0xFFFFFFFFu, s, off);
        if (lane == 0) g_score2[gw] = tanhf(s * g_invn2);
    }
}

// direct O(N^2) ranking for pool2 (4096 -> 256)
__global__ void k_rank2() {
    __shared__ float ss[KP1];
    for (int j = threadIdx.x; j < KP1; j += blockDim.x) ss[j] = g_score2[j];
    __syncthreads();
    int t = blockIdx.x * blockDim.x + threadIdx.x;   // exactly KP1 threads
    float s = ss[t];
    int r = 0;
    for (int j = 0; j < KP1; j++) {
        float v = ss[j];
        if (v > s) r++;
        else if (v == s && j < t) r++;
    }
    if (r < KP2) { g_perm2[r] = t; g_sc2[r] = s; }
}

// out += v @ fcW with v built on the fly: v[f*256+n] = x3[perm2[n]][f]*sc2[n]
// 512 blocks; block b covers v-range [b*128, b*128+128) => f = b>>1, n = (b&1)*128 ..
__global__ void __launch_bounds__(256) k_fc(const float* __restrict__ fcW,
                                            float* __restrict__ out) {
    __shared__ float sv[128];
    __shared__ float4 sacc[128];
    int b = blockIdx.x;
    int f = b >> 1;
    int n0 = (b & 1) << 7;
    int t = threadIdx.x;
    if (t < 128) {
        int n = n0 + t;
        sv[t] = g_x3[g_perm2[n] * 256 + f] * g_sc2[n];
    }
    __syncthreads();
    int sub = t >> 7, o4 = t & 127;
    const float4* fw = (const float4*)fcW;
    float4 acc = make_float4(0.f, 0.f, 0.f, 0.f);
    size_t base = ((size_t)b * 128 + (size_t)sub * 64) * 128 + o4;
    #pragma unroll 16
    for (int j = 0; j < 64; j++) {
        float s = sv[sub * 64 + j];
        float4 w = __ldcs(&fw[base + (size_t)j * 128]);
        acc.x += s * w.x; acc.y += s * w.y; acc.z += s * w.z; acc.w += s * w.w;
    }
    if (sub == 1) sacc[o4] = acc;
    __syncthreads();
    if (sub == 0) {
        float4 o = sacc[o4];
        acc.x += o.x; acc.y += o.y; acc.z += o.z; acc.w += o.w;
        atomicAdd(((float4*)out) + o4, acc);
    }
}

// ---------------- launch ----------------
extern "C" void kernel_launch(void* const* d_in, const int* in_sizes, int n_in,
                              void* d_out, int out_size) {
    const float* pos = (const float*)d_in[0];
    const int*   ei  = (const int*)d_in[1];     // int32 (JAX default, no x64)
    const float* W1 = (const float*)d_in[2];
    const float* b1 = (const float*)d_in[3];
    const float* W2 = (const float*)d_in[4];
    const float* b2 = (const float*)d_in[5];
    const float* W3 = (const float*)d_in[6];
    const float* b3 = (const float*)d_in[7];
    const float* p1 = (const float*)d_in[8];
    const float* p2 = (const float*)d_in[9];
    const float* fcW = (const float*)d_in[10];
    const float* fcb = (const float*)d_in[11];
    float* out = (float*)d_out;

    const int EB = (N_EDGES + 255) / 256;
    const int NB = (N_NODES + 255) / 256;

    k_init<<<2048, 256>>>(pos, p1, p2, fcb, out);
    k_edge_deg<<<EB, 256>>>(ei);
    k_agg3<<<EB, 256>>>();
    k_probe<<<512, 256>>>(fcW);          // launch #4 -> profiled by ncu
    k_score1<<<NB, 256>>>(W1, b1, p1);
    k_scan16<<<1, 1024>>>();
    k_compact<<<NB, 256>>>();
    k_rank1<<<32, 256>>>();
    k_gather1<<<KP1, 64>>>(W1, b1);
    k_ecompact<<<EB, 256>>>();
    k_escat64<<<256, 256>>>();
    k_gemm2<<<128, 128>>>(W2, b2);
    k_escat128<<<256, 256>>>();
    k_gemm3<<<256, 256>>>(W3, b3);
    k_score2<<<512, 256>>>(p2);
    k_rank2<<<16, 256>>>();
    k_fc<<<512, 256>>>(fcW, out);
}